// round 11
// baseline (speedup 1.0000x reference)
#include <cuda_runtime.h>
#include <cuda_bf16.h>
#include <cstdint>

// Problem dims — FIXED by the dataset (reference hardcodes them).
#define N_NODES 100000
#define N_EDGES 1600000
#define IN_C    128
#define HID_C   128
#define OUT_C   40

#define WPB     8     // warps per block in fused agg kernel
#define WPAD    136   // padded W1 row stride (floats) -> conflict-free B frags
#define GEMM1_BLOCKS ((N_NODES + 127) / 128)   // 782

// ---------------- scratch (static __device__ globals; no allocation) --------
__device__ float g_h1 [(size_t)N_NODES * HID_C];   // 51.2 MB: x @ W1 (no iso)
__device__ float g_t  [(size_t)N_NODES * OUT_C];   // 16 MB
__device__ int   g_degi[N_NODES];                  // in-degree
__device__ int   g_dego[N_NODES];                  // out-degree
__device__ float g_iso[N_NODES];                   // out-degree^{-1/2}
__device__ float g_isi[N_NODES];                   // in-degree^{-1/2}
__device__ int   g_src[N_EDGES];
__device__ int   g_dst[N_EDGES];
__device__ int   g_row[N_NODES];                   // CSR segment start (by dst)
__device__ int   g_cur[N_NODES];                   // fill cursors
__device__ int   g_eidx[N_EDGES];                  // CSR: src ids grouped by dst
__device__ int   g_mode;                           // edge dtype
__device__ int   g_total;                          // CSR allocation counter

// ---------------- helpers ----------------------------------------------------
__device__ __forceinline__ uint32_t f2tf32(float v) {
    uint32_t r;
    asm("cvt.rna.tf32.f32 %0, %1;" : "=r"(r) : "f"(v));
    return r;
}

// ---------------- zero + dtype probe (fused) ----------------------------------
__global__ void k_zero_detect(const int* __restrict__ w32) {
    int i = blockIdx.x * blockDim.x + threadIdx.x;
    if (i < N_NODES) { g_degi[i] = 0; g_dego[i] = 0; }
    if (i == 0) {
        g_total = 0;
        int oz = 0, ez = 0, ir = 0;
        for (int k = 0; k < 512; k++) {
            int w = w32[k];
            if (w == 0) { if (k & 1) oz++; else ez++; }
            if (w >= 0 && w < N_NODES) ir++;
        }
        int mode;
        if (oz > 240)      mode = 1;   // int64
        else if (ez > 240) mode = 3;   // float64
        else if (ir > 500) mode = 0;   // int32
        else               mode = 2;   // float32
        g_mode = mode;
    }
}

__global__ void k_convert(const void* __restrict__ ei) {
    int i = blockIdx.x * blockDim.x + threadIdx.x;
    if (i >= 2 * N_EDGES) return;
    int mode = g_mode;
    long long v;
    if (mode == 1)      v = ((const long long*)ei)[i];
    else if (mode == 0) v = (long long)((const int*)ei)[i];
    else if (mode == 2) v = (long long)((const float*)ei)[i];
    else                v = (long long)((const double*)ei)[i];
    int vi = (int)v;
    if (vi < 0) vi = 0;
    if (vi >= N_NODES) vi = N_NODES - 1;
    if (i < N_EDGES) { g_src[i] = vi;           atomicAdd(&g_dego[vi], 1); }
    else             { g_dst[i - N_EDGES] = vi; atomicAdd(&g_degi[vi], 1); }
}

// ---------------- norms + CSR segment allocation (fused) ---------------------
__global__ void k_isqrt_alloc() {
    int i = blockIdx.x * blockDim.x + threadIdx.x;
    if (i >= N_NODES) return;
    g_iso[i] = rsqrtf((float)max(g_dego[i], 1));
    g_isi[i] = rsqrtf((float)max(g_degi[i], 1));
    int pos = atomicAdd(&g_total, g_degi[i]);
    g_row[i] = pos;
    g_cur[i] = pos;
}

__global__ void k_fill() {
    int e = blockIdx.x * blockDim.x + threadIdx.x;
    if (e >= N_EDGES) return;
    int d = g_dst[e];
    int pos = atomicAdd(&g_cur[d], 1);
    g_eidx[pos] = g_src[e];
}

// ---------------- GEMM1 (tf32 tensor core): h1 = x @ W1 (NO iso) ------------
// Depends only on x, W1 -> runs concurrently with the CSR prep chain.
__global__ __launch_bounds__(256)
void k_gemm1_tf32(const float* __restrict__ x, const float* __restrict__ W) {
    extern __shared__ uint32_t Ws[];   // [128][WPAD] tf32 bits, 69.6 KB
    const int t = threadIdx.x;
    const int wid = t >> 5;
    const int lane = t & 31;

    #pragma unroll
    for (int i = 0; i < (IN_C * HID_C) / 256; i++) {
        int item = i * 256 + t;
        int kr = item >> 7, nc = item & 127;
        Ws[kr * WPAD + nc] = f2tf32(W[item]);
    }
    __syncthreads();

    const int row0 = blockIdx.x * 128 + wid * 16 + (lane >> 2);
    const int row1 = row0 + 8;
    const int rc0 = min(row0, N_NODES - 1);
    const int rc1 = min(row1, N_NODES - 1);
    const float* __restrict__ xr0 = x + (size_t)rc0 * IN_C + (lane & 3);
    const float* __restrict__ xr1 = x + (size_t)rc1 * IN_C + (lane & 3);

    float acc[16][4];
    #pragma unroll
    for (int n = 0; n < 16; n++)
        #pragma unroll
        for (int c = 0; c < 4; c++) acc[n][c] = 0.f;

    #pragma unroll 2
    for (int ks = 0; ks < 16; ks++) {
        const int k0 = ks * 8;
        uint32_t a0 = f2tf32(xr0[k0]);
        uint32_t a1 = f2tf32(xr1[k0]);
        uint32_t a2 = f2tf32(xr0[k0 + 4]);
        uint32_t a3 = f2tf32(xr1[k0 + 4]);
        const uint32_t* bb0 = Ws + (k0 + (lane & 3)) * WPAD + (lane >> 2);
        const uint32_t* bb1 = bb0 + 4 * WPAD;
        #pragma unroll
        for (int n = 0; n < 16; n++) {
            uint32_t b0 = bb0[n * 8];
            uint32_t b1 = bb1[n * 8];
            asm volatile(
                "mma.sync.aligned.m16n8k8.row.col.f32.tf32.tf32.f32 "
                "{%0,%1,%2,%3}, {%4,%5,%6,%7}, {%8,%9}, {%0,%1,%2,%3};"
                : "+f"(acc[n][0]), "+f"(acc[n][1]), "+f"(acc[n][2]), "+f"(acc[n][3])
                : "r"(a0), "r"(a1), "r"(a2), "r"(a3), "r"(b0), "r"(b1));
        }
    }

    const int colb = (lane & 3) * 2;
    #pragma unroll
    for (int n = 0; n < 16; n++) {
        int col = n * 8 + colb;
        if (row0 < N_NODES)
            *reinterpret_cast<float2*>(g_h1 + (size_t)row0 * HID_C + col) =
                make_float2(acc[n][0], acc[n][1]);
        if (row1 < N_NODES)
            *reinterpret_cast<float2*>(g_h1 + (size_t)row1 * HID_C + col) =
                make_float2(acc[n][2], acc[n][3]);
    }
}

// ---------------- FUSED: agg1 (iso-weighted) + relu/norm + GEMM2 ------------
__global__ __launch_bounds__(WPB * 32)
void k_agg1_gemm2(const float* __restrict__ W2) {
    __shared__ float W2s[HID_C][OUT_C];            // 20 KB, loaded once
    __shared__ __align__(16) float as[WPB][HID_C]; // per-warp staged row

    const int t = threadIdx.x;
    #pragma unroll
    for (int i = 0; i < (HID_C * OUT_C) / (WPB * 32); i++) {
        int item = i * (WPB * 32) + t;
        ((float*)W2s)[item] = W2[item];
    }
    __syncthreads();

    const int wid = t >> 5;
    const int lane = t & 31;
    const int d = blockIdx.x * WPB + wid;
    if (d >= N_NODES) return;

    const int beg = g_row[d];
    const int end = beg + g_degi[d];
    float4 acc = make_float4(0.f, 0.f, 0.f, 0.f);
    for (int j = beg; j < end; j++) {
        int s = g_eidx[j];                 // warp-uniform -> broadcast
        float fs = g_iso[s];               // warp-uniform (iso applied here now)
        float4 v = *(reinterpret_cast<const float4*>(g_h1 + (size_t)s * HID_C) + lane);
        acc.x += fs * v.x; acc.y += fs * v.y;
        acc.z += fs * v.z; acc.w += fs * v.w;
    }
    const float sc = g_iso[d] * g_isi[d];
    acc.x = fmaxf(acc.x, 0.f) * sc;
    acc.y = fmaxf(acc.y, 0.f) * sc;
    acc.z = fmaxf(acc.z, 0.f) * sc;
    acc.w = fmaxf(acc.w, 0.f) * sc;
    *reinterpret_cast<float4*>(&as[wid][lane * 4]) = acc;
    __syncwarp();

    float acc0 = 0.f, acc1 = 0.f;
    #pragma unroll 8
    for (int k4 = 0; k4 < HID_C / 4; k4++) {
        float4 h4 = *reinterpret_cast<const float4*>(&as[wid][k4 * 4]);
        float hv[4] = {h4.x, h4.y, h4.z, h4.w};
        #pragma unroll
        for (int c = 0; c < 4; c++) {
            int k = k4 * 4 + c;
            acc0 += hv[c] * W2s[k][lane];
            if (lane < 8) acc1 += hv[c] * W2s[k][32 + lane];
        }
    }
    g_t[(size_t)d * OUT_C + lane] = acc0;
    if (lane < 8) g_t[(size_t)d * OUT_C + 32 + lane] = acc1;
}

// ---------------- gather 2: out[d] = isi[d] * sum g_t[s], 3 nodes/warp ------
__global__ __launch_bounds__(256)
void k_agg2(float* __restrict__ out) {
    int gw = (blockIdx.x * blockDim.x + threadIdx.x) >> 5;
    int lane = threadIdx.x & 31;
    int sub = lane / 10;                 // 0,1,2 (lanes 30,31 idle)
    int c = lane - sub * 10;             // float4 chunk 0..9
    int d = gw * 3 + sub;
    if (sub >= 3 || d >= N_NODES) return;
    int beg = g_row[d];
    int end = beg + g_degi[d];
    float4 acc = make_float4(0.f, 0.f, 0.f, 0.f);
    for (int j = beg; j < end; j++) {
        int s = g_eidx[j];
        float4 v = *reinterpret_cast<const float4*>(g_t + (size_t)s * OUT_C + c * 4);
        acc.x += v.x; acc.y += v.y; acc.z += v.z; acc.w += v.w;
    }
    float sc = g_isi[d];
    acc.x *= sc; acc.y *= sc; acc.z *= sc; acc.w *= sc;
    *reinterpret_cast<float4*>(out + (size_t)d * OUT_C + c * 4) = acc;
}

// ---------------- launch ----------------------------------------------------
extern "C" void kernel_launch(void* const* d_in, const int* in_sizes, int n_in,
                              void* d_out, int out_size) {
    const float* x  = (const float*)d_in[0];
    const void*  ei = d_in[1];
    const float* W1 = (const float*)d_in[2];
    const float* W2 = (const float*)d_in[3];
    float* out = (float*)d_out;

    // One-time side-stream / event setup (not device memory; capture-legal)
    static cudaStream_t s_side = nullptr;
    static cudaEvent_t ev_fork = nullptr, ev_join = nullptr;
    static int smem_cfg = 0;
    const int smem1 = IN_C * WPAD * 4;   // 69632 B
    if (!s_side) {
        cudaStreamCreateWithFlags(&s_side, cudaStreamNonBlocking);
        cudaEventCreateWithFlags(&ev_fork, cudaEventDisableTiming);
        cudaEventCreateWithFlags(&ev_join, cudaEventDisableTiming);
    }
    if (!smem_cfg) {
        cudaFuncSetAttribute(k_gemm1_tf32,
                             cudaFuncAttributeMaxDynamicSharedMemorySize, smem1);
        smem_cfg = 1;
    }

    // Fork: GEMM1 (x @ W1, no graph dependency) on the side stream
    cudaEventRecord(ev_fork, 0);
    cudaStreamWaitEvent(s_side, ev_fork, 0);
    k_gemm1_tf32<<<GEMM1_BLOCKS, 256, smem1, s_side>>>(x, W1);
    cudaEventRecord(ev_join, s_side);

    // Main stream: prep chain (zero+detect -> convert+deg -> norms+CSR -> fill)
    k_zero_detect<<<(N_NODES + 255) / 256, 256>>>((const int*)ei);
    k_convert<<<(2 * N_EDGES + 255) / 256, 256>>>(ei);
    k_isqrt_alloc<<<(N_NODES + 255) / 256, 256>>>();
    k_fill<<<(N_EDGES + 255) / 256, 256>>>();

    // Join: fused aggregation needs both h1 and the CSR
    cudaStreamWaitEvent(0, ev_join, 0);

    k_agg1_gemm2<<<(N_NODES + WPB - 1) / WPB, WPB * 32>>>(W2);

    {
        int warps = (N_NODES + 2) / 3;
        int blocks = (warps * 32 + 255) / 256;
        k_agg2<<<blocks, 256>>>(out);
    }
}

// round 12
// speedup vs baseline: 1.0472x; 1.0472x over previous
#include <cuda_runtime.h>
#include <cuda_bf16.h>
#include <cstdint>

// Problem dims — FIXED by the dataset (reference hardcodes them).
#define N_NODES 100000
#define N_EDGES 1600000
#define IN_C    128
#define HID_C   128
#define OUT_C   40

#define WPB     8     // warps per block in fused agg kernel
#define WPAD    136   // padded W1 row stride (floats) -> conflict-free B frags
#define GEMM1_BLOCKS ((N_NODES + 127) / 128)   // 782
#define CAP     96    // bucket capacity per node (P(deg>=96) < 1e-40)

// ---------------- scratch (static __device__ globals; no allocation) --------
__device__ float g_h1 [(size_t)N_NODES * HID_C];   // 51.2 MB: x @ W1 (no iso)
__device__ float g_t  [(size_t)N_NODES * OUT_C];   // 16 MB
__device__ int   g_bkt[(size_t)N_NODES * CAP];     // 38.4 MB: src ids per dst
__device__ int   g_degi[N_NODES];                  // in-degree (= fill cursor)
__device__ int   g_dego[N_NODES];                  // out-degree
__device__ float g_iso[N_NODES];                   // out-degree^{-1/2}
__device__ float g_isi[N_NODES];                   // in-degree^{-1/2}
__device__ int   g_mode;                           // edge dtype

// ---------------- helpers ----------------------------------------------------
__device__ __forceinline__ uint32_t f2tf32(float v) {
    uint32_t r;
    asm("cvt.rna.tf32.f32 %0, %1;" : "=r"(r) : "f"(v));
    return r;
}

// ---------------- zero + dtype probe (fused) ---------------------------------
__global__ void k_zero_detect(const int* __restrict__ w32) {
    int i = blockIdx.x * blockDim.x + threadIdx.x;
    if (i < N_NODES) { g_degi[i] = 0; g_dego[i] = 0; }
    if (i == 0) {
        int oz = 0, ez = 0, ir = 0;
        for (int k = 0; k < 512; k++) {
            int w = w32[k];
            if (w == 0) { if (k & 1) oz++; else ez++; }
            if (w >= 0 && w < N_NODES) ir++;
        }
        int mode;
        if (oz > 240)      mode = 1;   // int64
        else if (ez > 240) mode = 3;   // float64
        else if (ir > 500) mode = 0;   // int32
        else               mode = 2;   // float32
        g_mode = mode;
    }
}

// ---------------- ONE PASS: decode + out-degree histogram + bucket fill ------
__global__ void k_convert_fill(const void* __restrict__ ei) {
    int e = blockIdx.x * blockDim.x + threadIdx.x;
    if (e >= N_EDGES) return;
    const int mode = g_mode;
    long long vs, vd;
    if (mode == 1)      { vs = ((const long long*)ei)[e]; vd = ((const long long*)ei)[N_EDGES + e]; }
    else if (mode == 0) { vs = ((const int*)ei)[e];       vd = ((const int*)ei)[N_EDGES + e]; }
    else if (mode == 2) { vs = (long long)((const float*)ei)[e];  vd = (long long)((const float*)ei)[N_EDGES + e]; }
    else                { vs = (long long)((const double*)ei)[e]; vd = (long long)((const double*)ei)[N_EDGES + e]; }
    int s = (int)vs, d = (int)vd;
    if (s < 0) s = 0; if (s >= N_NODES) s = N_NODES - 1;
    if (d < 0) d = 0; if (d >= N_NODES) d = N_NODES - 1;
    atomicAdd(&g_dego[s], 1);
    int pos = atomicAdd(&g_degi[d], 1);
    if (pos < CAP) g_bkt[(size_t)d * CAP + pos] = s;
}

// ---------------- norms ------------------------------------------------------
__global__ void k_isqrt() {
    int i = blockIdx.x * blockDim.x + threadIdx.x;
    if (i >= N_NODES) return;
    g_iso[i] = rsqrtf((float)max(g_dego[i], 1));
    g_isi[i] = rsqrtf((float)max(g_degi[i], 1));
}

// ---------------- GEMM1 (tf32 tensor core): h1 = x @ W1 (NO iso) ------------
// Depends only on x, W1 -> forked onto a side stream.
__global__ __launch_bounds__(256)
void k_gemm1_tf32(const float* __restrict__ x, const float* __restrict__ W) {
    extern __shared__ uint32_t Ws[];   // [128][WPAD] tf32 bits, 69.6 KB
    const int t = threadIdx.x;
    const int wid = t >> 5;
    const int lane = t & 31;

    #pragma unroll
    for (int i = 0; i < (IN_C * HID_C) / 256; i++) {
        int item = i * 256 + t;
        int kr = item >> 7, nc = item & 127;
        Ws[kr * WPAD + nc] = f2tf32(W[item]);
    }
    __syncthreads();

    const int row0 = blockIdx.x * 128 + wid * 16 + (lane >> 2);
    const int row1 = row0 + 8;
    const int rc0 = min(row0, N_NODES - 1);
    const int rc1 = min(row1, N_NODES - 1);
    const float* __restrict__ xr0 = x + (size_t)rc0 * IN_C + (lane & 3);
    const float* __restrict__ xr1 = x + (size_t)rc1 * IN_C + (lane & 3);

    float acc[16][4];
    #pragma unroll
    for (int n = 0; n < 16; n++)
        #pragma unroll
        for (int c = 0; c < 4; c++) acc[n][c] = 0.f;

    #pragma unroll 2
    for (int ks = 0; ks < 16; ks++) {
        const int k0 = ks * 8;
        uint32_t a0 = f2tf32(xr0[k0]);
        uint32_t a1 = f2tf32(xr1[k0]);
        uint32_t a2 = f2tf32(xr0[k0 + 4]);
        uint32_t a3 = f2tf32(xr1[k0 + 4]);
        const uint32_t* bb0 = Ws + (k0 + (lane & 3)) * WPAD + (lane >> 2);
        const uint32_t* bb1 = bb0 + 4 * WPAD;
        #pragma unroll
        for (int n = 0; n < 16; n++) {
            uint32_t b0 = bb0[n * 8];
            uint32_t b1 = bb1[n * 8];
            asm volatile(
                "mma.sync.aligned.m16n8k8.row.col.f32.tf32.tf32.f32 "
                "{%0,%1,%2,%3}, {%4,%5,%6,%7}, {%8,%9}, {%0,%1,%2,%3};"
                : "+f"(acc[n][0]), "+f"(acc[n][1]), "+f"(acc[n][2]), "+f"(acc[n][3])
                : "r"(a0), "r"(a1), "r"(a2), "r"(a3), "r"(b0), "r"(b1));
        }
    }

    const int colb = (lane & 3) * 2;
    #pragma unroll
    for (int n = 0; n < 16; n++) {
        int col = n * 8 + colb;
        if (row0 < N_NODES)
            *reinterpret_cast<float2*>(g_h1 + (size_t)row0 * HID_C + col) =
                make_float2(acc[n][0], acc[n][1]);
        if (row1 < N_NODES)
            *reinterpret_cast<float2*>(g_h1 + (size_t)row1 * HID_C + col) =
                make_float2(acc[n][2], acc[n][3]);
    }
}

// ---------------- FUSED: agg1 (iso-weighted, unroll-2) + relu/norm + GEMM2 --
__global__ __launch_bounds__(WPB * 32)
void k_agg1_gemm2(const float* __restrict__ W2) {
    __shared__ float W2s[HID_C][OUT_C];            // 20 KB, loaded once
    __shared__ __align__(16) float as[WPB][HID_C]; // per-warp staged row

    const int t = threadIdx.x;
    #pragma unroll
    for (int i = 0; i < (HID_C * OUT_C) / (WPB * 32); i++) {
        int item = i * (WPB * 32) + t;
        ((float*)W2s)[item] = W2[item];
    }
    __syncthreads();

    const int wid = t >> 5;
    const int lane = t & 31;
    const int d = blockIdx.x * WPB + wid;
    if (d >= N_NODES) return;

    const int* __restrict__ bp = g_bkt + (size_t)d * CAP;
    const int deg = min(g_degi[d], CAP);
    float4 acc  = make_float4(0.f, 0.f, 0.f, 0.f);
    float4 accB = make_float4(0.f, 0.f, 0.f, 0.f);
    int j = 0;
    for (; j + 1 < deg; j += 2) {              // two rows in flight
        int s0 = bp[j], s1 = bp[j + 1];        // warp-uniform
        float f0 = g_iso[s0], f1 = g_iso[s1];
        float4 v0 = *(reinterpret_cast<const float4*>(g_h1 + (size_t)s0 * HID_C) + lane);
        float4 v1 = *(reinterpret_cast<const float4*>(g_h1 + (size_t)s1 * HID_C) + lane);
        acc.x  += f0 * v0.x; acc.y  += f0 * v0.y; acc.z  += f0 * v0.z; acc.w  += f0 * v0.w;
        accB.x += f1 * v1.x; accB.y += f1 * v1.y; accB.z += f1 * v1.z; accB.w += f1 * v1.w;
    }
    if (j < deg) {
        int s0 = bp[j];
        float f0 = g_iso[s0];
        float4 v0 = *(reinterpret_cast<const float4*>(g_h1 + (size_t)s0 * HID_C) + lane);
        acc.x += f0 * v0.x; acc.y += f0 * v0.y; acc.z += f0 * v0.z; acc.w += f0 * v0.w;
    }
    acc.x += accB.x; acc.y += accB.y; acc.z += accB.z; acc.w += accB.w;

    const float sc = g_iso[d] * g_isi[d];
    acc.x = fmaxf(acc.x, 0.f) * sc;
    acc.y = fmaxf(acc.y, 0.f) * sc;
    acc.z = fmaxf(acc.z, 0.f) * sc;
    acc.w = fmaxf(acc.w, 0.f) * sc;
    *reinterpret_cast<float4*>(&as[wid][lane * 4]) = acc;
    __syncwarp();

    float acc0 = 0.f, acc1 = 0.f;
    #pragma unroll 8
    for (int k4 = 0; k4 < HID_C / 4; k4++) {
        float4 h4 = *reinterpret_cast<const float4*>(&as[wid][k4 * 4]);
        float hv[4] = {h4.x, h4.y, h4.z, h4.w};
        #pragma unroll
        for (int c = 0; c < 4; c++) {
            int k = k4 * 4 + c;
            acc0 += hv[c] * W2s[k][lane];
            if (lane < 8) acc1 += hv[c] * W2s[k][32 + lane];
        }
    }
    g_t[(size_t)d * OUT_C + lane] = acc0;
    if (lane < 8) g_t[(size_t)d * OUT_C + 32 + lane] = acc1;
}

// ---------------- gather 2: out[d] = isi[d]*sum g_t[s], 3 nodes/warp, x2 ----
__global__ __launch_bounds__(256)
void k_agg2(float* __restrict__ out) {
    int gw = (blockIdx.x * blockDim.x + threadIdx.x) >> 5;
    int lane = threadIdx.x & 31;
    int sub = lane / 10;                 // 0,1,2 (lanes 30,31 idle)
    int c = lane - sub * 10;             // float4 chunk 0..9
    int d = gw * 3 + sub;
    if (sub >= 3 || d >= N_NODES) return;
    const int* __restrict__ bp = g_bkt + (size_t)d * CAP;
    const int deg = min(g_degi[d], CAP);
    float4 acc  = make_float4(0.f, 0.f, 0.f, 0.f);
    float4 accB = make_float4(0.f, 0.f, 0.f, 0.f);
    int j = 0;
    for (; j + 1 < deg; j += 2) {
        int s0 = bp[j], s1 = bp[j + 1];
        float4 v0 = *reinterpret_cast<const float4*>(g_t + (size_t)s0 * OUT_C + c * 4);
        float4 v1 = *reinterpret_cast<const float4*>(g_t + (size_t)s1 * OUT_C + c * 4);
        acc.x  += v0.x; acc.y  += v0.y; acc.z  += v0.z; acc.w  += v0.w;
        accB.x += v1.x; accB.y += v1.y; accB.z += v1.z; accB.w += v1.w;
    }
    if (j < deg) {
        int s0 = bp[j];
        float4 v0 = *reinterpret_cast<const float4*>(g_t + (size_t)s0 * OUT_C + c * 4);
        acc.x += v0.x; acc.y += v0.y; acc.z += v0.z; acc.w += v0.w;
    }
    float sc = g_isi[d];
    acc.x = (acc.x + accB.x) * sc;
    acc.y = (acc.y + accB.y) * sc;
    acc.z = (acc.z + accB.z) * sc;
    acc.w = (acc.w + accB.w) * sc;
    *reinterpret_cast<float4*>(out + (size_t)d * OUT_C + c * 4) = acc;
}

// ---------------- launch ----------------------------------------------------
extern "C" void kernel_launch(void* const* d_in, const int* in_sizes, int n_in,
                              void* d_out, int out_size) {
    const float* x  = (const float*)d_in[0];
    const void*  ei = d_in[1];
    const float* W1 = (const float*)d_in[2];
    const float* W2 = (const float*)d_in[3];
    float* out = (float*)d_out;

    // One-time side-stream / event setup (no device memory; capture-legal)
    static cudaStream_t s_side = nullptr;
    static cudaEvent_t ev_fork = nullptr, ev_join = nullptr;
    static int smem_cfg = 0;
    const int smem1 = IN_C * WPAD * 4;   // 69632 B
    if (!s_side) {
        cudaStreamCreateWithFlags(&s_side, cudaStreamNonBlocking);
        cudaEventCreateWithFlags(&ev_fork, cudaEventDisableTiming);
        cudaEventCreateWithFlags(&ev_join, cudaEventDisableTiming);
    }
    if (!smem_cfg) {
        cudaFuncSetAttribute(k_gemm1_tf32,
                             cudaFuncAttributeMaxDynamicSharedMemorySize, smem1);
        smem_cfg = 1;
    }

    // Fork: GEMM1 (x @ W1) on the side stream
    cudaEventRecord(ev_fork, 0);
    cudaStreamWaitEvent(s_side, ev_fork, 0);
    k_gemm1_tf32<<<GEMM1_BLOCKS, 256, smem1, s_side>>>(x, W1);
    cudaEventRecord(ev_join, s_side);

    // Main stream: zero+detect -> one-pass decode/histogram/bucket-fill -> norms
    k_zero_detect<<<(N_NODES + 255) / 256, 256>>>((const int*)ei);
    k_convert_fill<<<(N_EDGES + 255) / 256, 256>>>(ei);
    k_isqrt<<<(N_NODES + 255) / 256, 256>>>();

    // Join: fused aggregation needs both h1 and the buckets
    cudaStreamWaitEvent(0, ev_join, 0);

    k_agg1_gemm2<<<(N_NODES + WPB - 1) / WPB, WPB * 32>>>(W2);

    {
        int warps = (N_NODES + 2) / 3;
        int blocks = (warps * 32 + 255) / 256;
        k_agg2<<<blocks, 256>>>(out);
    }
}

// round 13
// speedup vs baseline: 1.1152x; 1.0650x over previous
#include <cuda_runtime.h>
#include <cuda_bf16.h>
#include <cuda_fp16.h>
#include <cstdint>

// Problem dims — FIXED by the dataset (reference hardcodes them).
#define N_NODES 100000
#define N_EDGES 1600000
#define IN_C    128
#define HID_C   128
#define OUT_C   40

#define WPB     8     // warps per block in fused agg kernel
#define WPAD    136   // padded W1 row stride (floats) -> conflict-free B frags
#define GEMM1_BLOCKS ((N_NODES + 127) / 128)   // 782
#define CAP     96    // bucket capacity per node (P(deg>=96) < 1e-40)

// ---------------- scratch (static __device__ globals; no allocation) --------
__device__ __half g_h1h[(size_t)N_NODES * HID_C]; // 25.6 MB: x @ W1 (fp16)
__device__ __half g_th [(size_t)N_NODES * OUT_C]; // 8 MB: layer-2 proj (fp16)
__device__ int    g_bkt[(size_t)N_NODES * CAP];   // 38.4 MB: src ids per dst
__device__ int    g_degi[N_NODES];                // in-degree (= fill cursor)
__device__ int    g_dego[N_NODES];                // out-degree
__device__ float  g_iso[N_NODES];                 // out-degree^{-1/2}
__device__ float  g_isi[N_NODES];                 // in-degree^{-1/2}
__device__ int    g_mode;                         // edge dtype

// ---------------- helpers ----------------------------------------------------
__device__ __forceinline__ uint32_t f2tf32(float v) {
    uint32_t r;
    asm("cvt.rna.tf32.f32 %0, %1;" : "=r"(r) : "f"(v));
    return r;
}

// ---------------- zero + dtype probe (fused) ---------------------------------
__global__ void k_zero_detect(const int* __restrict__ w32) {
    int i = blockIdx.x * blockDim.x + threadIdx.x;
    if (i < N_NODES) { g_degi[i] = 0; g_dego[i] = 0; }
    if (i == 0) {
        int oz = 0, ez = 0, ir = 0;
        for (int k = 0; k < 512; k++) {
            int w = w32[k];
            if (w == 0) { if (k & 1) oz++; else ez++; }
            if (w >= 0 && w < N_NODES) ir++;
        }
        int mode;
        if (oz > 240)      mode = 1;   // int64
        else if (ez > 240) mode = 3;   // float64
        else if (ir > 500) mode = 0;   // int32
        else               mode = 2;   // float32
        g_mode = mode;
    }
}

// ---------------- ONE PASS: decode + out-degree histogram + bucket fill ------
__global__ void k_convert_fill(const void* __restrict__ ei) {
    int e = blockIdx.x * blockDim.x + threadIdx.x;
    if (e >= N_EDGES) return;
    const int mode = g_mode;
    long long vs, vd;
    if (mode == 1)      { vs = ((const long long*)ei)[e]; vd = ((const long long*)ei)[N_EDGES + e]; }
    else if (mode == 0) { vs = ((const int*)ei)[e];       vd = ((const int*)ei)[N_EDGES + e]; }
    else if (mode == 2) { vs = (long long)((const float*)ei)[e];  vd = (long long)((const float*)ei)[N_EDGES + e]; }
    else                { vs = (long long)((const double*)ei)[e]; vd = (long long)((const double*)ei)[N_EDGES + e]; }
    int s = (int)vs, d = (int)vd;
    if (s < 0) s = 0; if (s >= N_NODES) s = N_NODES - 1;
    if (d < 0) d = 0; if (d >= N_NODES) d = N_NODES - 1;
    atomicAdd(&g_dego[s], 1);
    int pos = atomicAdd(&g_degi[d], 1);
    if (pos < CAP) g_bkt[(size_t)d * CAP + pos] = s;
}

// ---------------- norms ------------------------------------------------------
__global__ void k_isqrt() {
    int i = blockIdx.x * blockDim.x + threadIdx.x;
    if (i >= N_NODES) return;
    g_iso[i] = rsqrtf((float)max(g_dego[i], 1));
    g_isi[i] = rsqrtf((float)max(g_degi[i], 1));
}

// ---------------- GEMM1 (tf32 tensor core): h1 = x @ W1 -> fp16 -------------
// Depends only on x, W1 -> forked onto a side stream.
__global__ __launch_bounds__(256)
void k_gemm1_tf32(const float* __restrict__ x, const float* __restrict__ W) {
    extern __shared__ uint32_t Ws[];   // [128][WPAD] tf32 bits, 69.6 KB
    const int t = threadIdx.x;
    const int wid = t >> 5;
    const int lane = t & 31;

    #pragma unroll
    for (int i = 0; i < (IN_C * HID_C) / 256; i++) {
        int item = i * 256 + t;
        int kr = item >> 7, nc = item & 127;
        Ws[kr * WPAD + nc] = f2tf32(W[item]);
    }
    __syncthreads();

    const int row0 = blockIdx.x * 128 + wid * 16 + (lane >> 2);
    const int row1 = row0 + 8;
    const int rc0 = min(row0, N_NODES - 1);
    const int rc1 = min(row1, N_NODES - 1);
    const float* __restrict__ xr0 = x + (size_t)rc0 * IN_C + (lane & 3);
    const float* __restrict__ xr1 = x + (size_t)rc1 * IN_C + (lane & 3);

    float acc[16][4];
    #pragma unroll
    for (int n = 0; n < 16; n++)
        #pragma unroll
        for (int c = 0; c < 4; c++) acc[n][c] = 0.f;

    #pragma unroll 2
    for (int ks = 0; ks < 16; ks++) {
        const int k0 = ks * 8;
        uint32_t a0 = f2tf32(xr0[k0]);
        uint32_t a1 = f2tf32(xr1[k0]);
        uint32_t a2 = f2tf32(xr0[k0 + 4]);
        uint32_t a3 = f2tf32(xr1[k0 + 4]);
        const uint32_t* bb0 = Ws + (k0 + (lane & 3)) * WPAD + (lane >> 2);
        const uint32_t* bb1 = bb0 + 4 * WPAD;
        #pragma unroll
        for (int n = 0; n < 16; n++) {
            uint32_t b0 = bb0[n * 8];
            uint32_t b1 = bb1[n * 8];
            asm volatile(
                "mma.sync.aligned.m16n8k8.row.col.f32.tf32.tf32.f32 "
                "{%0,%1,%2,%3}, {%4,%5,%6,%7}, {%8,%9}, {%0,%1,%2,%3};"
                : "+f"(acc[n][0]), "+f"(acc[n][1]), "+f"(acc[n][2]), "+f"(acc[n][3])
                : "r"(a0), "r"(a1), "r"(a2), "r"(a3), "r"(b0), "r"(b1));
        }
    }

    // Epilogue: adjacent col pairs -> one half2 store each
    const int colb = (lane & 3) * 2;
    #pragma unroll
    for (int n = 0; n < 16; n++) {
        int col = n * 8 + colb;
        if (row0 < N_NODES)
            *reinterpret_cast<__half2*>(g_h1h + (size_t)row0 * HID_C + col) =
                __floats2half2_rn(acc[n][0], acc[n][1]);
        if (row1 < N_NODES)
            *reinterpret_cast<__half2*>(g_h1h + (size_t)row1 * HID_C + col) =
                __floats2half2_rn(acc[n][2], acc[n][3]);
    }
}

// ---------------- FUSED: agg1 (iso-weighted, fp16 rows) + relu/norm + GEMM2 -
__global__ __launch_bounds__(WPB * 32)
void k_agg1_gemm2(const float* __restrict__ W2) {
    __shared__ float W2s[HID_C][OUT_C];            // 20 KB, loaded once
    __shared__ __align__(16) float as[WPB][HID_C]; // per-warp staged row (fp32)

    const int t = threadIdx.x;
    #pragma unroll
    for (int i = 0; i < (HID_C * OUT_C) / (WPB * 32); i++) {
        int item = i * (WPB * 32) + t;
        ((float*)W2s)[item] = W2[item];
    }
    __syncthreads();

    const int wid = t >> 5;
    const int lane = t & 31;
    const int d = blockIdx.x * WPB + wid;
    if (d >= N_NODES) return;

    const int* __restrict__ bp = g_bkt + (size_t)d * CAP;
    const int deg = min(g_degi[d], CAP);
    // lane owns channels lane*4 .. lane*4+3 (one uint2 = 2 half2 per row)
    float4 acc  = make_float4(0.f, 0.f, 0.f, 0.f);
    float4 accB = make_float4(0.f, 0.f, 0.f, 0.f);
    int j = 0;
    for (; j + 1 < deg; j += 2) {              // two rows in flight
        int s0 = bp[j], s1 = bp[j + 1];        // warp-uniform
        float f0 = g_iso[s0], f1 = g_iso[s1];
        uint2 u0 = *(reinterpret_cast<const uint2*>(g_h1h + (size_t)s0 * HID_C) + lane);
        uint2 u1 = *(reinterpret_cast<const uint2*>(g_h1h + (size_t)s1 * HID_C) + lane);
        float2 a0 = __half22float2(*reinterpret_cast<__half2*>(&u0.x));
        float2 a1 = __half22float2(*reinterpret_cast<__half2*>(&u0.y));
        float2 b0 = __half22float2(*reinterpret_cast<__half2*>(&u1.x));
        float2 b1 = __half22float2(*reinterpret_cast<__half2*>(&u1.y));
        acc.x  += f0 * a0.x; acc.y  += f0 * a0.y; acc.z  += f0 * a1.x; acc.w  += f0 * a1.y;
        accB.x += f1 * b0.x; accB.y += f1 * b0.y; accB.z += f1 * b1.x; accB.w += f1 * b1.y;
    }
    if (j < deg) {
        int s0 = bp[j];
        float f0 = g_iso[s0];
        uint2 u0 = *(reinterpret_cast<const uint2*>(g_h1h + (size_t)s0 * HID_C) + lane);
        float2 a0 = __half22float2(*reinterpret_cast<__half2*>(&u0.x));
        float2 a1 = __half22float2(*reinterpret_cast<__half2*>(&u0.y));
        acc.x += f0 * a0.x; acc.y += f0 * a0.y; acc.z += f0 * a1.x; acc.w += f0 * a1.y;
    }
    acc.x += accB.x; acc.y += accB.y; acc.z += accB.z; acc.w += accB.w;

    const float sc = g_iso[d] * g_isi[d];
    acc.x = fmaxf(acc.x, 0.f) * sc;
    acc.y = fmaxf(acc.y, 0.f) * sc;
    acc.z = fmaxf(acc.z, 0.f) * sc;
    acc.w = fmaxf(acc.w, 0.f) * sc;
    *reinterpret_cast<float4*>(&as[wid][lane * 4]) = acc;
    __syncwarp();

    float acc0 = 0.f, acc1 = 0.f;
    #pragma unroll 8
    for (int k4 = 0; k4 < HID_C / 4; k4++) {
        float4 h4 = *reinterpret_cast<const float4*>(&as[wid][k4 * 4]);
        float hv[4] = {h4.x, h4.y, h4.z, h4.w};
        #pragma unroll
        for (int c = 0; c < 4; c++) {
            int k = k4 * 4 + c;
            acc0 += hv[c] * W2s[k][lane];
            if (lane < 8) acc1 += hv[c] * W2s[k][32 + lane];
        }
    }
    g_th[(size_t)d * OUT_C + lane] = __float2half_rn(acc0);
    if (lane < 8) g_th[(size_t)d * OUT_C + 32 + lane] = __float2half_rn(acc1);
}

// ---------------- gather 2: out[d] = isi[d]*sum g_t[s], 3 nodes/warp, x2 ----
__global__ __launch_bounds__(256)
void k_agg2(float* __restrict__ out) {
    int gw = (blockIdx.x * blockDim.x + threadIdx.x) >> 5;
    int lane = threadIdx.x & 31;
    int sub = lane / 10;                 // 0,1,2 (lanes 30,31 idle)
    int c = lane - sub * 10;             // 4-col chunk 0..9 (uint2 of halfs)
    int d = gw * 3 + sub;
    if (sub >= 3 || d >= N_NODES) return;
    const int* __restrict__ bp = g_bkt + (size_t)d * CAP;
    const int deg = min(g_degi[d], CAP);
    float4 acc  = make_float4(0.f, 0.f, 0.f, 0.f);
    float4 accB = make_float4(0.f, 0.f, 0.f, 0.f);
    int j = 0;
    for (; j + 1 < deg; j += 2) {
        int s0 = bp[j], s1 = bp[j + 1];
        uint2 u0 = *(reinterpret_cast<const uint2*>(g_th + (size_t)s0 * OUT_C) + c);
        uint2 u1 = *(reinterpret_cast<const uint2*>(g_th + (size_t)s1 * OUT_C) + c);
        float2 a0 = __half22float2(*reinterpret_cast<__half2*>(&u0.x));
        float2 a1 = __half22float2(*reinterpret_cast<__half2*>(&u0.y));
        float2 b0 = __half22float2(*reinterpret_cast<__half2*>(&u1.x));
        float2 b1 = __half22float2(*reinterpret_cast<__half2*>(&u1.y));
        acc.x  += a0.x; acc.y  += a0.y; acc.z  += a1.x; acc.w  += a1.y;
        accB.x += b0.x; accB.y += b0.y; accB.z += b1.x; accB.w += b1.y;
    }
    if (j < deg) {
        int s0 = bp[j];
        uint2 u0 = *(reinterpret_cast<const uint2*>(g_th + (size_t)s0 * OUT_C) + c);
        float2 a0 = __half22float2(*reinterpret_cast<__half2*>(&u0.x));
        float2 a1 = __half22float2(*reinterpret_cast<__half2*>(&u0.y));
        acc.x += a0.x; acc.y += a0.y; acc.z += a1.x; acc.w += a1.y;
    }
    float sc = g_isi[d];
    acc.x = (acc.x + accB.x) * sc;
    acc.y = (acc.y + accB.y) * sc;
    acc.z = (acc.z + accB.z) * sc;
    acc.w = (acc.w + accB.w) * sc;
    *reinterpret_cast<float4*>(out + (size_t)d * OUT_C + c * 4) = acc;
}

// ---------------- launch ----------------------------------------------------
extern "C" void kernel_launch(void* const* d_in, const int* in_sizes, int n_in,
                              void* d_out, int out_size) {
    const float* x  = (const float*)d_in[0];
    const void*  ei = d_in[1];
    const float* W1 = (const float*)d_in[2];
    const float* W2 = (const float*)d_in[3];
    float* out = (float*)d_out;

    // One-time side-stream / event setup (no device memory; capture-legal)
    static cudaStream_t s_side = nullptr;
    static cudaEvent_t ev_fork = nullptr, ev_join = nullptr;
    static int smem_cfg = 0;
    const int smem1 = IN_C * WPAD * 4;   // 69632 B
    if (!s_side) {
        cudaStreamCreateWithFlags(&s_side, cudaStreamNonBlocking);
        cudaEventCreateWithFlags(&ev_fork, cudaEventDisableTiming);
        cudaEventCreateWithFlags(&ev_join, cudaEventDisableTiming);
    }
    if (!smem_cfg) {
        cudaFuncSetAttribute(k_gemm1_tf32,
                             cudaFuncAttributeMaxDynamicSharedMemorySize, smem1);
        smem_cfg = 1;
    }

    // Fork: GEMM1 (x @ W1) on the side stream
    cudaEventRecord(ev_fork, 0);
    cudaStreamWaitEvent(s_side, ev_fork, 0);
    k_gemm1_tf32<<<GEMM1_BLOCKS, 256, smem1, s_side>>>(x, W1);
    cudaEventRecord(ev_join, s_side);

    // Main stream: zero+detect -> one-pass decode/histogram/bucket-fill -> norms
    k_zero_detect<<<(N_NODES + 255) / 256, 256>>>((const int*)ei);
    k_convert_fill<<<(N_EDGES + 255) / 256, 256>>>(ei);
    k_isqrt<<<(N_NODES + 255) / 256, 256>>>();

    // Join: fused aggregation needs both h1 and the buckets
    cudaStreamWaitEvent(0, ev_join, 0);

    k_agg1_gemm2<<<(N_NODES + WPB - 1) / WPB, WPB * 32>>>(W2);

    {
        int warps = (N_NODES + 2) / 3;
        int blocks = (warps * 32 + 255) / 256;
        k_agg2<<<blocks, 256>>>(out);
    }
}

// round 14
// speedup vs baseline: 1.6386x; 1.4693x over previous
#include <cuda_runtime.h>
#include <cuda_bf16.h>
#include <cuda_fp16.h>
#include <cstdint>

// Problem dims — FIXED by the dataset (reference hardcodes them).
#define N_NODES 100000
#define N_EDGES 1600000
#define IN_C    128
#define HID_C   128
#define OUT_C   40

#define WPB     16    // nodes (=warps) per block in fused agg kernel (100000%16==0)
#define WPAD    136   // padded W1 row stride (floats) -> conflict-free B frags
#define APAD    132   // padded as row stride -> conflict-free A frags
#define GEMM1_BLOCKS ((N_NODES + 127) / 128)   // 782
#define CAP     96    // bucket capacity per node (P(deg>=96) < 1e-40)

// ---------------- scratch (static __device__ globals; no allocation) --------
__device__ __half g_h1h[(size_t)N_NODES * HID_C]; // 25.6 MB: x @ W1 (fp16)
__device__ __half g_th [(size_t)N_NODES * OUT_C]; // 8 MB: layer-2 proj (fp16)
__device__ int    g_bkt[(size_t)N_NODES * CAP];   // 38.4 MB: src ids per dst
__device__ int    g_degi[N_NODES];                // in-degree (= fill cursor)
__device__ int    g_dego[N_NODES];                // out-degree
__device__ float  g_iso[N_NODES];                 // out-degree^{-1/2}
__device__ float  g_isi[N_NODES];                 // in-degree^{-1/2}
__device__ int    g_mode;                         // edge dtype

// ---------------- helpers ----------------------------------------------------
__device__ __forceinline__ uint32_t f2tf32(float v) {
    uint32_t r;
    asm("cvt.rna.tf32.f32 %0, %1;" : "=r"(r) : "f"(v));
    return r;
}

// ---------------- zero + dtype probe (fused) ---------------------------------
__global__ void k_zero_detect(const int* __restrict__ w32) {
    int i = blockIdx.x * blockDim.x + threadIdx.x;
    if (i < N_NODES) { g_degi[i] = 0; g_dego[i] = 0; }
    if (i == 0) {
        int oz = 0, ez = 0, ir = 0;
        for (int k = 0; k < 512; k++) {
            int w = w32[k];
            if (w == 0) { if (k & 1) oz++; else ez++; }
            if (w >= 0 && w < N_NODES) ir++;
        }
        int mode;
        if (oz > 240)      mode = 1;   // int64
        else if (ez > 240) mode = 3;   // float64
        else if (ir > 500) mode = 0;   // int32
        else               mode = 2;   // float32
        g_mode = mode;
    }
}

// ---------------- ONE PASS: decode + out-degree histogram + bucket fill ------
__global__ void k_convert_fill(const void* __restrict__ ei) {
    int e = blockIdx.x * blockDim.x + threadIdx.x;
    if (e >= N_EDGES) return;
    const int mode = g_mode;
    long long vs, vd;
    if (mode == 1)      { vs = ((const long long*)ei)[e]; vd = ((const long long*)ei)[N_EDGES + e]; }
    else if (mode == 0) { vs = ((const int*)ei)[e];       vd = ((const int*)ei)[N_EDGES + e]; }
    else if (mode == 2) { vs = (long long)((const float*)ei)[e];  vd = (long long)((const float*)ei)[N_EDGES + e]; }
    else                { vs = (long long)((const double*)ei)[e]; vd = (long long)((const double*)ei)[N_EDGES + e]; }
    int s = (int)vs, d = (int)vd;
    if (s < 0) s = 0; if (s >= N_NODES) s = N_NODES - 1;
    if (d < 0) d = 0; if (d >= N_NODES) d = N_NODES - 1;
    atomicAdd(&g_dego[s], 1);
    int pos = atomicAdd(&g_degi[d], 1);
    if (pos < CAP) g_bkt[(size_t)d * CAP + pos] = s;
}

// ---------------- norms ------------------------------------------------------
__global__ void k_isqrt() {
    int i = blockIdx.x * blockDim.x + threadIdx.x;
    if (i >= N_NODES) return;
    g_iso[i] = rsqrtf((float)max(g_dego[i], 1));
    g_isi[i] = rsqrtf((float)max(g_degi[i], 1));
}

// ---------------- GEMM1 (tf32 tensor core): h1 = x @ W1 -> fp16 -------------
// Depends only on x, W1 -> forked onto a side stream.
__global__ __launch_bounds__(256)
void k_gemm1_tf32(const float* __restrict__ x, const float* __restrict__ W) {
    extern __shared__ uint32_t Ws[];   // [128][WPAD] tf32 bits, 69.6 KB
    const int t = threadIdx.x;
    const int wid = t >> 5;
    const int lane = t & 31;

    #pragma unroll
    for (int i = 0; i < (IN_C * HID_C) / 256; i++) {
        int item = i * 256 + t;
        int kr = item >> 7, nc = item & 127;
        Ws[kr * WPAD + nc] = f2tf32(W[item]);
    }
    __syncthreads();

    const int row0 = blockIdx.x * 128 + wid * 16 + (lane >> 2);
    const int row1 = row0 + 8;
    const int rc0 = min(row0, N_NODES - 1);
    const int rc1 = min(row1, N_NODES - 1);
    const float* __restrict__ xr0 = x + (size_t)rc0 * IN_C + (lane & 3);
    const float* __restrict__ xr1 = x + (size_t)rc1 * IN_C + (lane & 3);

    float acc[16][4];
    #pragma unroll
    for (int n = 0; n < 16; n++)
        #pragma unroll
        for (int c = 0; c < 4; c++) acc[n][c] = 0.f;

    #pragma unroll 2
    for (int ks = 0; ks < 16; ks++) {
        const int k0 = ks * 8;
        uint32_t a0 = f2tf32(xr0[k0]);
        uint32_t a1 = f2tf32(xr1[k0]);
        uint32_t a2 = f2tf32(xr0[k0 + 4]);
        uint32_t a3 = f2tf32(xr1[k0 + 4]);
        const uint32_t* bb0 = Ws + (k0 + (lane & 3)) * WPAD + (lane >> 2);
        const uint32_t* bb1 = bb0 + 4 * WPAD;
        #pragma unroll
        for (int n = 0; n < 16; n++) {
            uint32_t b0 = bb0[n * 8];
            uint32_t b1 = bb1[n * 8];
            asm volatile(
                "mma.sync.aligned.m16n8k8.row.col.f32.tf32.tf32.f32 "
                "{%0,%1,%2,%3}, {%4,%5,%6,%7}, {%8,%9}, {%0,%1,%2,%3};"
                : "+f"(acc[n][0]), "+f"(acc[n][1]), "+f"(acc[n][2]), "+f"(acc[n][3])
                : "r"(a0), "r"(a1), "r"(a2), "r"(a3), "r"(b0), "r"(b1));
        }
    }

    const int colb = (lane & 3) * 2;
    #pragma unroll
    for (int n = 0; n < 16; n++) {
        int col = n * 8 + colb;
        if (row0 < N_NODES)
            *reinterpret_cast<__half2*>(g_h1h + (size_t)row0 * HID_C + col) =
                __floats2half2_rn(acc[n][0], acc[n][1]);
        if (row1 < N_NODES)
            *reinterpret_cast<__half2*>(g_h1h + (size_t)row1 * HID_C + col) =
                __floats2half2_rn(acc[n][2], acc[n][3]);
    }
}

// ---------------- FUSED: agg1 (fp16 rows) + relu/norm + GEMM2 (tf32 MMA) ----
// 16 warps = 16 nodes per block. Gather phase: warp w -> node base+w, staged
// as tf32 bits into as_f. MMA phase: warps 0..4 each own an 8-col n-tile of
// the [16 x 128] @ [128 x 40] product.
__global__ __launch_bounds__(WPB * 32)
void k_agg1_gemm2(const float* __restrict__ W2) {
    __shared__ uint32_t W2s[HID_C * OUT_C];        // 20 KB tf32 bits ([k][40];
                                                   // 40%32==8 -> B frags conflict-free)
    __shared__ uint32_t as_f[WPB * APAD];          // 8.25 KB tf32 bits [16][132]

    const int t = threadIdx.x;
    const int wid = t >> 5;
    const int lane = t & 31;
    const int base = blockIdx.x * WPB;

    // Load + convert W2 once (5120 / 512 = 10 each, coalesced)
    #pragma unroll
    for (int i = 0; i < (HID_C * OUT_C) / (WPB * 32); i++)
        W2s[i * (WPB * 32) + t] = f2tf32(W2[i * (WPB * 32) + t]);

    // ---- gather phase (all 16 warps) ----
    const int d = base + wid;
    const int* __restrict__ bp = g_bkt + (size_t)d * CAP;
    const int deg = min(g_degi[d], CAP);
    float4 acc  = make_float4(0.f, 0.f, 0.f, 0.f);
    float4 accB = make_float4(0.f, 0.f, 0.f, 0.f);
    int j = 0;
    for (; j + 1 < deg; j += 2) {              // two rows in flight
        int s0 = bp[j], s1 = bp[j + 1];        // warp-uniform
        float f0 = g_iso[s0], f1 = g_iso[s1];
        uint2 u0 = *(reinterpret_cast<const uint2*>(g_h1h + (size_t)s0 * HID_C) + lane);
        uint2 u1 = *(reinterpret_cast<const uint2*>(g_h1h + (size_t)s1 * HID_C) + lane);
        float2 a0 = __half22float2(*reinterpret_cast<__half2*>(&u0.x));
        float2 a1 = __half22float2(*reinterpret_cast<__half2*>(&u0.y));
        float2 b0 = __half22float2(*reinterpret_cast<__half2*>(&u1.x));
        float2 b1 = __half22float2(*reinterpret_cast<__half2*>(&u1.y));
        acc.x  += f0 * a0.x; acc.y  += f0 * a0.y; acc.z  += f0 * a1.x; acc.w  += f0 * a1.y;
        accB.x += f1 * b0.x; accB.y += f1 * b0.y; accB.z += f1 * b1.x; accB.w += f1 * b1.y;
    }
    if (j < deg) {
        int s0 = bp[j];
        float f0 = g_iso[s0];
        uint2 u0 = *(reinterpret_cast<const uint2*>(g_h1h + (size_t)s0 * HID_C) + lane);
        float2 a0 = __half22float2(*reinterpret_cast<__half2*>(&u0.x));
        float2 a1 = __half22float2(*reinterpret_cast<__half2*>(&u0.y));
        acc.x += f0 * a0.x; acc.y += f0 * a0.y; acc.z += f0 * a1.x; acc.w += f0 * a1.y;
    }
    acc.x += accB.x; acc.y += accB.y; acc.z += accB.z; acc.w += accB.w;

    const float sc = g_iso[d] * g_isi[d];
    // relu + norm, stage as tf32 bits (lane owns channels lane*4..lane*4+3)
    as_f[wid * APAD + lane * 4 + 0] = f2tf32(fmaxf(acc.x, 0.f) * sc);
    as_f[wid * APAD + lane * 4 + 1] = f2tf32(fmaxf(acc.y, 0.f) * sc);
    as_f[wid * APAD + lane * 4 + 2] = f2tf32(fmaxf(acc.z, 0.f) * sc);
    as_f[wid * APAD + lane * 4 + 3] = f2tf32(fmaxf(acc.w, 0.f) * sc);
    __syncthreads();

    // ---- MMA phase (warps 0..4, n-tile = wid) ----
    if (wid < 5) {
        const int nt = wid;
        float c0 = 0.f, c1 = 0.f, c2 = 0.f, c3 = 0.f;
        const uint32_t* __restrict__ ap0 = as_f + (lane >> 2) * APAD + (lane & 3);
        const uint32_t* __restrict__ ap1 = ap0 + 8 * APAD;
        const uint32_t* __restrict__ bb  = W2s + (lane & 3) * OUT_C + nt * 8 + (lane >> 2);
        #pragma unroll
        for (int ks = 0; ks < 16; ks++) {
            const int k0 = ks * 8;
            uint32_t a0 = ap0[k0];
            uint32_t a1 = ap1[k0];
            uint32_t a2 = ap0[k0 + 4];
            uint32_t a3 = ap1[k0 + 4];
            uint32_t b0 = bb[k0 * OUT_C];
            uint32_t b1 = bb[(k0 + 4) * OUT_C];
            asm volatile(
                "mma.sync.aligned.m16n8k8.row.col.f32.tf32.tf32.f32 "
                "{%0,%1,%2,%3}, {%4,%5,%6,%7}, {%8,%9}, {%0,%1,%2,%3};"
                : "+f"(c0), "+f"(c1), "+f"(c2), "+f"(c3)
                : "r"(a0), "r"(a1), "r"(a2), "r"(a3), "r"(b0), "r"(b1));
        }
        // epilogue: rows lane>>2 and +8; cols nt*8 + 2*(lane&3), +1
        const int row0 = base + (lane >> 2);
        const int row1 = row0 + 8;
        const int col = nt * 8 + 2 * (lane & 3);
        *reinterpret_cast<__half2*>(g_th + (size_t)row0 * OUT_C + col) =
            __floats2half2_rn(c0, c1);
        *reinterpret_cast<__half2*>(g_th + (size_t)row1 * OUT_C + col) =
            __floats2half2_rn(c2, c3);
    }
}

// ---------------- gather 2: out[d] = isi[d]*sum g_t[s], 3 nodes/warp, x2 ----
__global__ __launch_bounds__(256)
void k_agg2(float* __restrict__ out) {
    int gw = (blockIdx.x * blockDim.x + threadIdx.x) >> 5;
    int lane = threadIdx.x & 31;
    int sub = lane / 10;                 // 0,1,2 (lanes 30,31 idle)
    int c = lane - sub * 10;             // 4-col chunk 0..9 (uint2 of halfs)
    int d = gw * 3 + sub;
    if (sub >= 3 || d >= N_NODES) return;
    const int* __restrict__ bp = g_bkt + (size_t)d * CAP;
    const int deg = min(g_degi[d], CAP);
    float4 acc  = make_float4(0.f, 0.f, 0.f, 0.f);
    float4 accB = make_float4(0.f, 0.f, 0.f, 0.f);
    int j = 0;
    for (; j + 1 < deg; j += 2) {
        int s0 = bp[j], s1 = bp[j + 1];
        uint2 u0 = *(reinterpret_cast<const uint2*>(g_th + (size_t)s0 * OUT_C) + c);
        uint2 u1 = *(reinterpret_cast<const uint2*>(g_th + (size_t)s1 * OUT_C) + c);
        float2 a0 = __half22float2(*reinterpret_cast<__half2*>(&u0.x));
        float2 a1 = __half22float2(*reinterpret_cast<__half2*>(&u0.y));
        float2 b0 = __half22float2(*reinterpret_cast<__half2*>(&u1.x));
        float2 b1 = __half22float2(*reinterpret_cast<__half2*>(&u1.y));
        acc.x  += a0.x; acc.y  += a0.y; acc.z  += a1.x; acc.w  += a1.y;
        accB.x += b0.x; accB.y += b0.y; accB.z += b1.x; accB.w += b1.y;
    }
    if (j < deg) {
        int s0 = bp[j];
        uint2 u0 = *(reinterpret_cast<const uint2*>(g_th + (size_t)s0 * OUT_C) + c);
        float2 a0 = __half22float2(*reinterpret_cast<__half2*>(&u0.x));
        float2 a1 = __half22float2(*reinterpret_cast<__half2*>(&u0.y));
        acc.x += a0.x; acc.y += a0.y; acc.z += a1.x; acc.w += a1.y;
    }
    float sc = g_isi[d];
    acc.x = (acc.x + accB.x) * sc;
    acc.y = (acc.y + accB.y) * sc;
    acc.z = (acc.z + accB.z) * sc;
    acc.w = (acc.w + accB.w) * sc;
    *reinterpret_cast<float4*>(out + (size_t)d * OUT_C + c * 4) = acc;
}

// ---------------- launch ----------------------------------------------------
extern "C" void kernel_launch(void* const* d_in, const int* in_sizes, int n_in,
                              void* d_out, int out_size) {
    const float* x  = (const float*)d_in[0];
    const void*  ei = d_in[1];
    const float* W1 = (const float*)d_in[2];
    const float* W2 = (const float*)d_in[3];
    float* out = (float*)d_out;

    // One-time side-stream / event setup (no device memory; capture-legal)
    static cudaStream_t s_side = nullptr;
    static cudaEvent_t ev_fork = nullptr, ev_join = nullptr;
    static int smem_cfg = 0;
    const int smem1 = IN_C * WPAD * 4;   // 69632 B
    if (!s_side) {
        cudaStreamCreateWithFlags(&s_side, cudaStreamNonBlocking);
        cudaEventCreateWithFlags(&ev_fork, cudaEventDisableTiming);
        cudaEventCreateWithFlags(&ev_join, cudaEventDisableTiming);
    }
    if (!smem_cfg) {
        cudaFuncSetAttribute(k_gemm1_tf32,
                             cudaFuncAttributeMaxDynamicSharedMemorySize, smem1);
        smem_cfg = 1;
    }

    // Fork: GEMM1 (x @ W1) on the side stream
    cudaEventRecord(ev_fork, 0);
    cudaStreamWaitEvent(s_side, ev_fork, 0);
    k_gemm1_tf32<<<GEMM1_BLOCKS, 256, smem1, s_side>>>(x, W1);
    cudaEventRecord(ev_join, s_side);

    // Main stream: zero+detect -> one-pass decode/histogram/bucket-fill -> norms
    k_zero_detect<<<(N_NODES + 255) / 256, 256>>>((const int*)ei);
    k_convert_fill<<<(N_EDGES + 255) / 256, 256>>>(ei);
    k_isqrt<<<(N_NODES + 255) / 256, 256>>>();

    // Join: fused aggregation needs both h1 and the buckets
    cudaStreamWaitEvent(0, ev_join, 0);

    k_agg1_gemm2<<<N_NODES / WPB, WPB * 32>>>(W2);

    {
        int warps = (N_NODES + 2) / 3;
        int blocks = (warps * 32 + 255) / 256;
        k_agg2<<<blocks, 256>>>(out);
    }
}